// round 7
// baseline (speedup 1.0000x reference)
#include <cuda_runtime.h>
#include <cstdint>

// Problem dims
#define B_DIM 32
#define S_DIM 2048
#define H_DIM 1024
#define NROWS (B_DIM * S_DIM)   // 65536

// ---------------- device scratch (no allocs allowed) ----------------
__device__ float g_scores[B_DIM * S_DIM];          // pre-softmax scores
__device__ float g_c[B_DIM * H_DIM];               // hW[b,k] + attn_b[k]
// We pair-packed + tf32-rounded: pair-row p = (h>>3)*4 + (h&3), sel = (h>>2)&1
//   g_WeB[(p*1024 + n)*2 + sel] = rna_tf32(We[n][h])   (float2 {B[k][n], B[k+4][n]})
__device__ float g_WeB[H_DIM * H_DIM];

// ---------------- helpers ----------------
__device__ __forceinline__ uint32_t smem_u32(const void* p) {
    uint32_t a;
    asm("{ .reg .u64 t; cvta.to.shared.u64 t, %1; cvt.u32.u64 %0, t; }"
        : "=r"(a) : "l"(p));
    return a;
}

__device__ __forceinline__ uint32_t f2tf32(float f) {
    uint32_t u;
    asm("cvt.rna.tf32.f32 %0, %1;" : "=r"(u) : "f"(f));
    return u;
}

// single-MUFU tanh (max err ~2^-11; fine vs 1e-3 gate with 1.9e-4 base)
__device__ __forceinline__ float tanh_fast(float x) {
    float y;
    asm("tanh.approx.f32 %0, %1;" : "=f"(y) : "f"(x));
    return y;
}

#define CP_ASYNC16(dst_u32, src_ptr) \
    asm volatile("cp.async.cg.shared.global [%0], [%1], 16;" \
                 :: "r"(dst_u32), "l"(src_ptr) : "memory")
#define CP_ASYNC_COMMIT() asm volatile("cp.async.commit_group;" ::: "memory")
#define CP_ASYNC_WAIT1()  asm volatile("cp.async.wait_group 1;" ::: "memory")
#define CP_ASYNC_WAIT0()  asm volatile("cp.async.wait_group 0;" ::: "memory")

__device__ __forceinline__ void mma_tf32(float d[4], const uint32_t a[4],
                                         const uint32_t b[2]) {
    asm volatile(
        "mma.sync.aligned.m16n8k8.row.col.f32.tf32.tf32.f32 "
        "{%0,%1,%2,%3}, {%4,%5,%6,%7}, {%8,%9}, {%0,%1,%2,%3};"
        : "+f"(d[0]), "+f"(d[1]), "+f"(d[2]), "+f"(d[3])
        : "r"(a[0]), "r"(a[1]), "r"(a[2]), "r"(a[3]), "r"(b[0]), "r"(b[1]));
}

// ---------------- kernel A: transpose + tf32-round + pair-pack We ----------------
__global__ void transpose_we_kernel(const float* __restrict__ attn_w) {
    __shared__ float t[32][33];
    int nb = blockIdx.x * 32, hb = blockIdx.y * 32;
    int x = threadIdx.x, y = threadIdx.y;   // 32 x 8
    #pragma unroll
    for (int j = 0; j < 4; j++)
        t[y + 8 * j][x] = attn_w[(size_t)(nb + y + 8 * j) * (2 * H_DIM) + H_DIM + hb + x];
    __syncthreads();
    #pragma unroll
    for (int j = 0; j < 4; j++) {
        int h = hb + y + 8 * j;
        int n = nb + x;
        int p = (h >> 3) * 4 + (h & 3);
        int sel = (h >> 2) & 1;
        g_WeB[((size_t)p * H_DIM + n) * 2 + sel] = __uint_as_float(f2tf32(t[x][y + 8 * j]));
    }
}

// ---------------- kernel 0: init output(hidden half) + zero scores ----------------
__global__ void init_kernel(const float* __restrict__ hidden, float* __restrict__ out) {
    int idx = blockIdx.x * 256 + threadIdx.x;          // 0..65535
    int b = idx >> 11;
    int c = idx & 2047;
    if (c >= H_DIM) out[idx] = hidden[b * H_DIM + (c - H_DIM)];
    g_scores[idx] = 0.0f;
}

// ---------------- kernel 1: c[b,k] = hidden @ Wh^T + attn_b  (tiled, smem) ----------
// grid 32 (k-chunks of 32), block 256: thread = (k_local = tid&31, bq = tid>>5),
// each thread owns (k, 4 batches). Wh read once (4MB), hidden ~4MB L2.
__global__ void cvec_kernel(const float* __restrict__ hidden,
                            const float* __restrict__ attn_w,
                            const float* __restrict__ attn_b) {
    __shared__ float whS[32][33];    // [k_local][hh]
    __shared__ float hdS[32][33];    // [b][hh]
    const int tid = threadIdx.x;
    const int kl = tid & 31, bq = tid >> 5;     // bq 0..7
    const int k0 = blockIdx.x * 32;
    float acc[4] = {0.f, 0.f, 0.f, 0.f};

    for (int h0 = 0; h0 < H_DIM; h0 += 32) {
        __syncthreads();
        // stage Wh[32k][32h]: thread (kl, bq): rows via bq*4..: 256 threads, 1024 words
        #pragma unroll
        for (int j = 0; j < 4; j++) {
            int r = bq * 4 + j;                  // k row 0..31
            whS[r][kl] = attn_w[(size_t)(k0 + r) * (2 * H_DIM) + h0 + kl];
            hdS[r][kl] = hidden[(size_t)r * H_DIM + h0 + kl];   // b row r
        }
        __syncthreads();
        #pragma unroll
        for (int hh = 0; hh < 32; hh++) {
            float wv = whS[kl][hh];
            #pragma unroll
            for (int j = 0; j < 4; j++)
                acc[j] = fmaf(wv, hdS[bq * 4 + j][hh], acc[j]);
        }
    }
    float bias = attn_b[k0 + kl];
    #pragma unroll
    for (int j = 0; j < 4; j++)
        g_c[(size_t)(bq * 4 + j) * H_DIM + k0 + kl] = acc[j] + bias;
}

// ---------------- kernel 2: fused tf32 mma.sync GEMM + tanh + v-dot ----------------
// CTA tile: M=128 rows x N=128 features, K=1024 (32 iters of KC=32).
// 4 warps (128 thr) as 2(m) x 2(n), warp tile 64x64 via m16n8k8. 2 CTAs/SM.
// A+B staged through a 3-slot cp.async ring (prefetch depth 2), 1 sync/iter.
static constexpr int NKITER = 32;
// smem word layout (floats):
//   c_sm [0,128)  v_sm [128,256)
//   3 stages x (A: 4096 words [128r x 32k, word = m*32 + (k ^ 4*(m&7))]
//               B: 4096 words [16 prow x 128 float2, f2idx = prow*128 + (col ^ 4*(prow&3))])
static constexpr int W_C  = 0;
static constexpr int W_V  = 128;
static constexpr int W_A  = 256;
static constexpr int STAGE_WORDS = 4096 + 4096;     // 8192
static constexpr int GEMM_SMEM_BYTES = (W_A + 3 * STAGE_WORDS) * 4;   // 99,328

__device__ __forceinline__ void load_stage(uint32_t smem_base, int slot,
                                           const float* __restrict__ enc,
                                           const float2* __restrict__ WeB2,
                                           int row0, int kg0, int it, int tid) {
    const int base_w = W_A + slot * STAGE_WORDS;
    const int hbase = it * 32;
    // A: 128 rows x 32 words = 1024 16B chunks, 8 per thread (128 threads)
    #pragma unroll
    for (int j = 0; j < 8; j++) {
        int c = tid + j * 128;
        int m = c >> 3, k0 = (c & 7) * 4;
        uint32_t w = (uint32_t)(base_w + m * 32 + (k0 ^ ((m & 7) * 4)));
        CP_ASYNC16(smem_base + w * 4, enc + (size_t)(row0 + m) * H_DIM + hbase + k0);
    }
    // B: 16 pair-rows x 128 float2 = 1024 16B chunks, 8 per thread
    #pragma unroll
    for (int j = 0; j < 8; j++) {
        int c = tid + j * 128;
        int prow = c >> 6, n0 = (c & 63) * 2;     // float2 index, 2 per chunk
        uint32_t f2i = (uint32_t)(prow * 128 + (n0 ^ (4 * (prow & 3))));
        uint32_t w = (uint32_t)(base_w + 4096) + f2i * 2;
        CP_ASYNC16(smem_base + w * 4,
                   WeB2 + (size_t)(it * 16 + prow) * H_DIM + kg0 + n0);
    }
}

__global__ void __launch_bounds__(128, 2)
gemm_scores_kernel(const float* __restrict__ enc,
                   const float* __restrict__ v_w) {
    extern __shared__ float smw[];
    uint32_t smem_base = smem_u32(smw);
    const int tid = threadIdx.x;
    const int wid = tid >> 5, lane = tid & 31;
    const int q = lane >> 2, t4 = lane & 3;
    const int wm = wid & 1, wn = wid >> 1;          // 2 x 2 warp grid
    const int row0 = blockIdx.y * 128;              // row-block (slow axis)
    const int b = row0 >> 11;
    const int kg0 = blockIdx.x * 128;               // n-chunk (fast axis -> L2 A reuse)

    const float2* __restrict__ WeB2 = reinterpret_cast<const float2*>(g_WeB);

    // prologue: stages 0..1 into slots 0..1
    load_stage(smem_base, 0, enc, WeB2, row0, kg0, 0, tid);
    CP_ASYNC_COMMIT();
    load_stage(smem_base, 1, enc, WeB2, row0, kg0, 1, tid);
    CP_ASYNC_COMMIT();

    // epilogue vectors (128 each)
    smw[W_C + tid] = g_c[b * H_DIM + kg0 + tid];
    smw[W_V + tid] = v_w[kg0 + tid];

    // accumulators: 4 m-tiles x 8 n-tiles x 4 regs = 128
    float d[4][8][4];
    #pragma unroll
    for (int mt = 0; mt < 4; mt++)
        #pragma unroll
        for (int nt = 0; nt < 8; nt++)
            #pragma unroll
            for (int r = 0; r < 4; r++) d[mt][nt][r] = 0.0f;

    for (int it = 0; it < NKITER; it++) {
        CP_ASYNC_WAIT1();          // stage `it` resident (<=1 younger pending)
        __syncthreads();           // visibility + all warps done with stage it-1

        if (it + 2 < NKITER) {
            int slot = (it + 2) % 3;
            load_stage(smem_base, slot, enc, WeB2, row0, kg0, it + 2, tid);
        }
        CP_ASYNC_COMMIT();

        const int bufA = W_A + (it % 3) * STAGE_WORDS;
        const float2* bufB = reinterpret_cast<const float2*>(smw + bufA + 4096);

        #pragma unroll
        for (int ks = 0; ks < 4; ks++) {
            // A fragments: one ldmatrix.x4 per mt
            uint32_t a[4][4];
            #pragma unroll
            for (int mt = 0; mt < 4; mt++) {
                int m = wm * 64 + mt * 16 + (lane & 15);
                int chk = ks * 2 + (lane >> 4);            // 16B chunk index in row
                uint32_t w = (uint32_t)(bufA + m * 32 + ((chk * 4) ^ ((m & 7) * 4)));
                uint32_t addr = smem_base + w * 4;
                asm volatile(
                    "ldmatrix.sync.aligned.m8n8.x4.shared.b16 {%0,%1,%2,%3}, [%4];"
                    : "=r"(a[mt][0]), "=r"(a[mt][1]), "=r"(a[mt][2]), "=r"(a[mt][3])
                    : "r"(addr));
            }
            // B fragments: one LDS.64 per nt from pair-packed stage
            const int prow_l = ks * 4 + t4;
            uint32_t bb[8][2];
            #pragma unroll
            for (int nt = 0; nt < 8; nt++) {
                int col = wn * 64 + nt * 8 + q;
                float2 v = bufB[prow_l * 128 + (col ^ (4 * t4))];
                bb[nt][0] = __float_as_uint(v.x);
                bb[nt][1] = __float_as_uint(v.y);
            }
            #pragma unroll
            for (int mt = 0; mt < 4; mt++)
                #pragma unroll
                for (int nt = 0; nt < 8; nt++)
                    mma_tf32(d[mt][nt], a[mt], bb[nt]);
        }
    }
    CP_ASYNC_WAIT0();

    // Epilogue: score[r] += sum_n v[n] * tanh(d + c[n])
    #pragma unroll
    for (int mt = 0; mt < 4; mt++) {
        float s0 = 0.0f, s1 = 0.0f;
        #pragma unroll
        for (int nt = 0; nt < 8; nt++) {
            int n = wn * 64 + nt * 8 + t4 * 2;
            float c0 = smw[W_C + n], c1 = smw[W_C + n + 1];
            float v0 = smw[W_V + n], v1 = smw[W_V + n + 1];
            s0 = fmaf(tanh_fast(d[mt][nt][0] + c0), v0, s0);
            s0 = fmaf(tanh_fast(d[mt][nt][1] + c1), v1, s0);
            s1 = fmaf(tanh_fast(d[mt][nt][2] + c0), v0, s1);
            s1 = fmaf(tanh_fast(d[mt][nt][3] + c1), v1, s1);
        }
        #pragma unroll
        for (int o = 1; o < 4; o <<= 1) {
            s0 += __shfl_xor_sync(0xffffffffu, s0, o);
            s1 += __shfl_xor_sync(0xffffffffu, s1, o);
        }
        if (t4 == 0) {
            int r = row0 + wm * 64 + mt * 16 + q;
            atomicAdd(&g_scores[r], s0);
            atomicAdd(&g_scores[r + 8], s1);
        }
    }
}

// ---------------- kernel 3: softmax over S per batch ----------------
__global__ void softmax_kernel(float* __restrict__ outw) {
    __shared__ float sh[S_DIM];
    __shared__ float red[256];
    int b = blockIdx.x, tid = threadIdx.x;
    float lmax = -1e30f;
    for (int i = tid; i < S_DIM; i += 256) {
        float v = g_scores[b * S_DIM + i];
        sh[i] = v;
        lmax = fmaxf(lmax, v);
    }
    red[tid] = lmax;
    __syncthreads();
    for (int s = 128; s > 0; s >>= 1) {
        if (tid < s) red[tid] = fmaxf(red[tid], red[tid + s]);
        __syncthreads();
    }
    float m = red[0];
    __syncthreads();
    float lsum = 0.0f;
    for (int i = tid; i < S_DIM; i += 256) {
        float e = expf(sh[i] - m);
        sh[i] = e;
        lsum += e;
    }
    red[tid] = lsum;
    __syncthreads();
    for (int s = 128; s > 0; s >>= 1) {
        if (tid < s) red[tid] += red[tid + s];
        __syncthreads();
    }
    float inv = 1.0f / red[0];
    for (int i = tid; i < S_DIM; i += 256) outw[b * S_DIM + i] = sh[i] * inv;
}

// ---------------- kernel 4: context, atomic-free ----------------
// grid (32 b, 8 h-chunks of 128), block 256 = 8 s-groups x 32 lanes, float4/lane.
__global__ void context_kernel(const float* __restrict__ enc,
                               const float* __restrict__ w,
                               float* __restrict__ out) {
    __shared__ float4 red[8][32];
    const int b = blockIdx.x, hc = blockIdx.y;
    const int tg = threadIdx.x >> 5, lane = threadIdx.x & 31;
    const float4* e4 = reinterpret_cast<const float4*>(
        enc + (size_t)b * S_DIM * H_DIM + hc * 128) + lane;
    const float* wr = w + b * S_DIM;
    float ax = 0.f, ay = 0.f, az = 0.f, aw = 0.f;
    #pragma unroll 4
    for (int s = tg; s < S_DIM; s += 8) {
        float wv = wr[s];
        float4 ev = e4[(size_t)s * 256];
        ax = fmaf(wv, ev.x, ax); ay = fmaf(wv, ev.y, ay);
        az = fmaf(wv, ev.z, az); aw = fmaf(wv, ev.w, aw);
    }
    red[tg][lane] = make_float4(ax, ay, az, aw);
    __syncthreads();
    if (tg == 0) {
        float4 a = red[0][lane];
        #pragma unroll
        for (int g = 1; g < 8; g++) {
            float4 r = red[g][lane];
            a.x += r.x; a.y += r.y; a.z += r.z; a.w += r.w;
        }
        reinterpret_cast<float4*>(out + b * (2 * H_DIM) + hc * 128)[lane] = a;
    }
}

// ---------------- launcher ----------------
extern "C" void kernel_launch(void* const* d_in, const int* in_sizes, int n_in,
                              void* d_out, int out_size) {
    const float* hidden = (const float*)d_in[0];   // (32, 1024)
    const float* enc    = (const float*)d_in[1];   // (32, 2048, 1024)
    const float* attn_w = (const float*)d_in[2];   // (1024, 2048)
    const float* attn_b = (const float*)d_in[3];   // (1024,)
    const float* v_w    = (const float*)d_in[4];   // (1, 1024)
    float* out = (float*)d_out;                    // [output (32,2048) | attn_w (32,2048,1)]

    cudaFuncSetAttribute(gemm_scores_kernel,
                         cudaFuncAttributeMaxDynamicSharedMemorySize,
                         GEMM_SMEM_BYTES);

    transpose_we_kernel<<<dim3(32, 32), dim3(32, 8)>>>(attn_w);
    init_kernel<<<256, 256>>>(hidden, out);
    cvec_kernel<<<32, 256>>>(hidden, attn_w, attn_b);
    gemm_scores_kernel<<<dim3(8, 512), 128, GEMM_SMEM_BYTES>>>(enc, v_w);
    softmax_kernel<<<32, 256>>>(out + B_DIM * S_DIM);
    context_kernel<<<dim3(32, 8), 256>>>(enc, out + B_DIM * S_DIM, out);
}

// round 8
// speedup vs baseline: 1.0995x; 1.0995x over previous
#include <cuda_runtime.h>
#include <cstdint>

// Problem dims
#define B_DIM 32
#define S_DIM 2048
#define H_DIM 1024
#define NROWS (B_DIM * S_DIM)   // 65536

// ---------------- device scratch (no allocs allowed) ----------------
__device__ float g_scores[B_DIM * S_DIM];          // pre-softmax scores
__device__ float g_c[B_DIM * H_DIM];               // hW[b,k] + attn_b[k]
// We pair-packed + tf32-rounded: pair-row p = (h>>3)*4 + (h&3), sel = (h>>2)&1
//   g_WeB[(p*1024 + n)*2 + sel] = rna_tf32(We[n][h])   (float2 {B[k][n], B[k+4][n]})
__device__ float g_WeB[H_DIM * H_DIM];

// ---------------- helpers ----------------
__device__ __forceinline__ uint32_t smem_u32(const void* p) {
    uint32_t a;
    asm("{ .reg .u64 t; cvta.to.shared.u64 t, %1; cvt.u32.u64 %0, t; }"
        : "=r"(a) : "l"(p));
    return a;
}

__device__ __forceinline__ uint32_t f2tf32(float f) {
    uint32_t u;
    asm("cvt.rna.tf32.f32 %0, %1;" : "=r"(u) : "f"(f));
    return u;
}

// single-MUFU tanh (max err ~2^-11; fine vs 1e-3 gate with 1.9e-4 base)
__device__ __forceinline__ float tanh_fast(float x) {
    float y;
    asm("tanh.approx.f32 %0, %1;" : "=f"(y) : "f"(x));
    return y;
}

#define CP_ASYNC16(dst_u32, src_ptr) \
    asm volatile("cp.async.cg.shared.global [%0], [%1], 16;" \
                 :: "r"(dst_u32), "l"(src_ptr) : "memory")
#define CP_ASYNC_COMMIT() asm volatile("cp.async.commit_group;" ::: "memory")
#define CP_ASYNC_WAIT1()  asm volatile("cp.async.wait_group 1;" ::: "memory")
#define CP_ASYNC_WAIT0()  asm volatile("cp.async.wait_group 0;" ::: "memory")

__device__ __forceinline__ void mma_tf32(float d[4], const uint32_t a[4],
                                         const uint32_t b[2]) {
    asm volatile(
        "mma.sync.aligned.m16n8k8.row.col.f32.tf32.tf32.f32 "
        "{%0,%1,%2,%3}, {%4,%5,%6,%7}, {%8,%9}, {%0,%1,%2,%3};"
        : "+f"(d[0]), "+f"(d[1]), "+f"(d[2]), "+f"(d[3])
        : "r"(a[0]), "r"(a[1]), "r"(a[2]), "r"(a[3]), "r"(b[0]), "r"(b[1]));
}

// ---------------- kernel A: transpose + tf32-round + pair-pack We ----------------
__global__ void transpose_we_kernel(const float* __restrict__ attn_w) {
    __shared__ float t[32][33];
    int nb = blockIdx.x * 32, hb = blockIdx.y * 32;
    int x = threadIdx.x, y = threadIdx.y;   // 32 x 8
    #pragma unroll
    for (int j = 0; j < 4; j++)
        t[y + 8 * j][x] = attn_w[(size_t)(nb + y + 8 * j) * (2 * H_DIM) + H_DIM + hb + x];
    __syncthreads();
    #pragma unroll
    for (int j = 0; j < 4; j++) {
        int h = hb + y + 8 * j;
        int n = nb + x;
        int p = (h >> 3) * 4 + (h & 3);
        int sel = (h >> 2) & 1;
        g_WeB[((size_t)p * H_DIM + n) * 2 + sel] = __uint_as_float(f2tf32(t[x][y + 8 * j]));
    }
}

// ---------------- kernel 0: init output + zero scores ----------------
__global__ void init_kernel(const float* __restrict__ hidden, float* __restrict__ out) {
    int idx = blockIdx.x * 256 + threadIdx.x;          // 0..65535
    int b = idx >> 11;
    int c = idx & 2047;
    out[idx] = (c < H_DIM) ? 0.0f : hidden[b * H_DIM + (c - H_DIM)];
    g_scores[idx] = 0.0f;
}

// ---------------- kernel 1: c[b,k] = hidden @ Wh^T + attn_b (warp-per-dot) -------
__global__ void cvec_kernel(const float* __restrict__ hidden,
                            const float* __restrict__ attn_w,
                            const float* __restrict__ attn_b) {
    int b = blockIdx.x;
    int wid = threadIdx.x >> 5, lane = threadIdx.x & 31;
    int k = blockIdx.y * 8 + wid;
    const float* hrow = hidden + b * H_DIM;
    const float* wrow = attn_w + (size_t)k * (2 * H_DIM);   // Wh row k
    float s = 0.0f;
    #pragma unroll 8
    for (int h = lane; h < H_DIM; h += 32) s += hrow[h] * wrow[h];
    #pragma unroll
    for (int o = 16; o > 0; o >>= 1) s += __shfl_xor_sync(0xffffffffu, s, o);
    if (lane == 0) g_c[b * H_DIM + k] = s + attn_b[k];
}

// ---------------- kernel 2: fused tf32 mma.sync GEMM + tanh + v-dot ----------------
// CTA tile: M=128 rows x N=128 features, K=1024 (32 iters of KC=32).
// 4 warps (128 thr) as 2(m) x 2(n), warp tile 64x64 via m16n8k8. 2 CTAs/SM.
// A+B staged through a 3-slot cp.async ring (prefetch depth 2), 1 sync/iter.
static constexpr int NKITER = 32;
// smem word layout (floats):
//   c_sm [0,128)  v_sm [128,256)
//   3 stages x (A: 4096 words [128r x 32k, word = m*32 + (k ^ 4*(m&7))]
//               B: 4096 words [16 prow x 128 float2, f2idx = prow*128 + (col ^ 4*(prow&3))])
static constexpr int W_C  = 0;
static constexpr int W_V  = 128;
static constexpr int W_A  = 256;
static constexpr int STAGE_WORDS = 4096 + 4096;     // 8192
static constexpr int GEMM_SMEM_BYTES = (W_A + 3 * STAGE_WORDS) * 4;   // 99,328

__device__ __forceinline__ void load_stage(uint32_t smem_base, int slot,
                                           const float* __restrict__ enc,
                                           const float2* __restrict__ WeB2,
                                           int row0, int kg0, int it, int tid) {
    const int base_w = W_A + slot * STAGE_WORDS;
    const int hbase = it * 32;
    // A: 128 rows x 32 words = 1024 16B chunks, 8 per thread (128 threads)
    #pragma unroll
    for (int j = 0; j < 8; j++) {
        int c = tid + j * 128;
        int m = c >> 3, k0 = (c & 7) * 4;
        uint32_t w = (uint32_t)(base_w + m * 32 + (k0 ^ ((m & 7) * 4)));
        CP_ASYNC16(smem_base + w * 4, enc + (size_t)(row0 + m) * H_DIM + hbase + k0);
    }
    // B: 16 pair-rows x 128 float2 = 1024 16B chunks, 8 per thread
    #pragma unroll
    for (int j = 0; j < 8; j++) {
        int c = tid + j * 128;
        int prow = c >> 6, n0 = (c & 63) * 2;     // float2 index, 2 per chunk
        uint32_t f2i = (uint32_t)(prow * 128 + (n0 ^ (4 * (prow & 3))));
        uint32_t w = (uint32_t)(base_w + 4096) + f2i * 2;
        CP_ASYNC16(smem_base + w * 4,
                   WeB2 + (size_t)(it * 16 + prow) * H_DIM + kg0 + n0);
    }
}

__global__ void __launch_bounds__(128, 2)
gemm_scores_kernel(const float* __restrict__ enc,
                   const float* __restrict__ v_w) {
    extern __shared__ float smw[];
    uint32_t smem_base = smem_u32(smw);
    const int tid = threadIdx.x;
    const int wid = tid >> 5, lane = tid & 31;
    const int q = lane >> 2, t4 = lane & 3;
    const int wm = wid & 1, wn = wid >> 1;          // 2 x 2 warp grid
    const int row0 = blockIdx.y * 128;              // row-block (slow axis)
    const int b = row0 >> 11;
    const int kg0 = blockIdx.x * 128;               // n-chunk (fast axis -> L2 A reuse)

    const float2* __restrict__ WeB2 = reinterpret_cast<const float2*>(g_WeB);

    // prologue: stages 0..1 into slots 0..1
    load_stage(smem_base, 0, enc, WeB2, row0, kg0, 0, tid);
    CP_ASYNC_COMMIT();
    load_stage(smem_base, 1, enc, WeB2, row0, kg0, 1, tid);
    CP_ASYNC_COMMIT();

    // epilogue vectors (128 each)
    smw[W_C + tid] = g_c[b * H_DIM + kg0 + tid];
    smw[W_V + tid] = v_w[kg0 + tid];

    // accumulators: 4 m-tiles x 8 n-tiles x 4 regs = 128
    float d[4][8][4];
    #pragma unroll
    for (int mt = 0; mt < 4; mt++)
        #pragma unroll
        for (int nt = 0; nt < 8; nt++)
            #pragma unroll
            for (int r = 0; r < 4; r++) d[mt][nt][r] = 0.0f;

    for (int it = 0; it < NKITER; it++) {
        CP_ASYNC_WAIT1();          // stage `it` resident (<=1 younger pending)
        __syncthreads();           // visibility + all warps done with stage it-1

        if (it + 2 < NKITER) {
            int slot = (it + 2) % 3;
            load_stage(smem_base, slot, enc, WeB2, row0, kg0, it + 2, tid);
        }
        CP_ASYNC_COMMIT();

        const int bufA = W_A + (it % 3) * STAGE_WORDS;
        const float2* bufB = reinterpret_cast<const float2*>(smw + bufA + 4096);

        #pragma unroll
        for (int ks = 0; ks < 4; ks++) {
            // A fragments: one ldmatrix.x4 per mt
            uint32_t a[4][4];
            #pragma unroll
            for (int mt = 0; mt < 4; mt++) {
                int m = wm * 64 + mt * 16 + (lane & 15);
                int chk = ks * 2 + (lane >> 4);            // 16B chunk index in row
                uint32_t w = (uint32_t)(bufA + m * 32 + ((chk * 4) ^ ((m & 7) * 4)));
                uint32_t addr = smem_base + w * 4;
                asm volatile(
                    "ldmatrix.sync.aligned.m8n8.x4.shared.b16 {%0,%1,%2,%3}, [%4];"
                    : "=r"(a[mt][0]), "=r"(a[mt][1]), "=r"(a[mt][2]), "=r"(a[mt][3])
                    : "r"(addr));
            }
            // B fragments: one LDS.64 per nt from pair-packed stage
            const int prow_l = ks * 4 + t4;
            uint32_t bb[8][2];
            #pragma unroll
            for (int nt = 0; nt < 8; nt++) {
                int col = wn * 64 + nt * 8 + q;
                float2 v = bufB[prow_l * 128 + (col ^ (4 * t4))];
                bb[nt][0] = __float_as_uint(v.x);
                bb[nt][1] = __float_as_uint(v.y);
            }
            #pragma unroll
            for (int mt = 0; mt < 4; mt++)
                #pragma unroll
                for (int nt = 0; nt < 8; nt++)
                    mma_tf32(d[mt][nt], a[mt], bb[nt]);
        }
    }
    CP_ASYNC_WAIT0();

    // Epilogue: score[r] += sum_n v[n] * tanh(d + c[n])
    #pragma unroll
    for (int mt = 0; mt < 4; mt++) {
        float s0 = 0.0f, s1 = 0.0f;
        #pragma unroll
        for (int nt = 0; nt < 8; nt++) {
            int n = wn * 64 + nt * 8 + t4 * 2;
            float c0 = smw[W_C + n], c1 = smw[W_C + n + 1];
            float v0 = smw[W_V + n], v1 = smw[W_V + n + 1];
            s0 = fmaf(tanh_fast(d[mt][nt][0] + c0), v0, s0);
            s0 = fmaf(tanh_fast(d[mt][nt][1] + c1), v1, s0);
            s1 = fmaf(tanh_fast(d[mt][nt][2] + c0), v0, s1);
            s1 = fmaf(tanh_fast(d[mt][nt][3] + c1), v1, s1);
        }
        #pragma unroll
        for (int o = 1; o < 4; o <<= 1) {
            s0 += __shfl_xor_sync(0xffffffffu, s0, o);
            s1 += __shfl_xor_sync(0xffffffffu, s1, o);
        }
        if (t4 == 0) {
            int r = row0 + wm * 64 + mt * 16 + q;
            atomicAdd(&g_scores[r], s0);
            atomicAdd(&g_scores[r + 8], s1);
        }
    }
}

// ---------------- kernel 3: softmax over S per batch ----------------
__global__ void softmax_kernel(float* __restrict__ outw) {
    __shared__ float sh[S_DIM];
    __shared__ float red[256];
    int b = blockIdx.x, tid = threadIdx.x;
    float lmax = -1e30f;
    for (int i = tid; i < S_DIM; i += 256) {
        float v = g_scores[b * S_DIM + i];
        sh[i] = v;
        lmax = fmaxf(lmax, v);
    }
    red[tid] = lmax;
    __syncthreads();
    for (int s = 128; s > 0; s >>= 1) {
        if (tid < s) red[tid] = fmaxf(red[tid], red[tid + s]);
        __syncthreads();
    }
    float m = red[0];
    __syncthreads();
    float lsum = 0.0f;
    for (int i = tid; i < S_DIM; i += 256) {
        float e = expf(sh[i] - m);
        sh[i] = e;
        lsum += e;
    }
    red[tid] = lsum;
    __syncthreads();
    for (int s = 128; s > 0; s >>= 1) {
        if (tid < s) red[tid] += red[tid + s];
        __syncthreads();
    }
    float inv = 1.0f / red[0];
    for (int i = tid; i < S_DIM; i += 256) outw[b * S_DIM + i] = sh[i] * inv;
}

// ---------------- kernel 4: context[b,h] = sum_s w[b,s] * enc[b,s,h] ----------------
__global__ void context_kernel(const float* __restrict__ enc,
                               const float* __restrict__ w,
                               float* __restrict__ out) {
    __shared__ float ws[128];
    int b = blockIdx.x, sc = blockIdx.y, tid = threadIdx.x;
    if (tid < 128) ws[tid] = w[b * S_DIM + sc * 128 + tid];
    __syncthreads();
    const float4* e4 = reinterpret_cast<const float4*>(
        enc + ((size_t)(b * S_DIM + sc * 128)) * H_DIM);
    float ax = 0.f, ay = 0.f, az = 0.f, aw = 0.f;
    #pragma unroll 4
    for (int s = 0; s < 128; s++) {
        float wv = ws[s];
        float4 ev = e4[(size_t)s * 256 + tid];
        ax += wv * ev.x; ay += wv * ev.y; az += wv * ev.z; aw += wv * ev.w;
    }
    float* o = out + b * (2 * H_DIM) + tid * 4;
    atomicAdd(o + 0, ax);
    atomicAdd(o + 1, ay);
    atomicAdd(o + 2, az);
    atomicAdd(o + 3, aw);
}

// ---------------- launcher ----------------
extern "C" void kernel_launch(void* const* d_in, const int* in_sizes, int n_in,
                              void* d_out, int out_size) {
    const float* hidden = (const float*)d_in[0];   // (32, 1024)
    const float* enc    = (const float*)d_in[1];   // (32, 2048, 1024)
    const float* attn_w = (const float*)d_in[2];   // (1024, 2048)
    const float* attn_b = (const float*)d_in[3];   // (1024,)
    const float* v_w    = (const float*)d_in[4];   // (1, 1024)
    float* out = (float*)d_out;                    // [output (32,2048) | attn_w (32,2048,1)]

    cudaFuncSetAttribute(gemm_scores_kernel,
                         cudaFuncAttributeMaxDynamicSharedMemorySize,
                         GEMM_SMEM_BYTES);

    transpose_we_kernel<<<dim3(32, 32), dim3(32, 8)>>>(attn_w);
    init_kernel<<<256, 256>>>(hidden, out);
    cvec_kernel<<<dim3(32, 128), 256>>>(hidden, attn_w, attn_b);
    gemm_scores_kernel<<<dim3(8, 512), 128, GEMM_SMEM_BYTES>>>(enc, v_w);
    softmax_kernel<<<32, 256>>>(out + B_DIM * S_DIM);
    context_kernel<<<dim3(32, 16), 256>>>(enc, out + B_DIM * S_DIM, out);
}